// round 13
// baseline (speedup 1.0000x reference)
#include <cuda_runtime.h>
#include <cuda_bf16.h>
#include <math.h>
#include <stdint.h>

// Problem constants
#define B_      2
#define S_      2048
#define DMODEL  2048
#define NH      16
#define DH      128
#define DLAT    512
#define DR      64
#define DQK     192            // DH + DR
#define KVD     320            // DH + DR + DH
#define QFD     3072           // NH * DQK
#define KVFD    5120           // NH * KVD
#define ROWS    (B_*S_)        // 4096

// ---- warp-level bf16 MMA (sm_80+, works at compute_100) ----
__device__ __forceinline__ void mma_bf16(float* c, const uint32_t* a, const uint32_t* b) {
    asm("mma.sync.aligned.m16n8k16.row.col.f32.bf16.bf16.f32 "
        "{%0,%1,%2,%3}, {%4,%5,%6,%7}, {%8,%9}, {%0,%1,%2,%3};"
        : "+f"(c[0]), "+f"(c[1]), "+f"(c[2]), "+f"(c[3])
        : "r"(a[0]), "r"(a[1]), "r"(a[2]), "r"(a[3]), "r"(b[0]), "r"(b[1]));
}
__device__ __forceinline__ void ldsm4(uint32_t* r, uint32_t a) {
    asm volatile("ldmatrix.sync.aligned.m8n8.x4.shared.b16 {%0,%1,%2,%3}, [%4];"
        : "=r"(r[0]), "=r"(r[1]), "=r"(r[2]), "=r"(r[3]) : "r"(a));
}

// ---- split helper: fp32 pair -> bf16 hi/lo words ----
__device__ __forceinline__ void split_pair(float a, float b, uint32_t& hw, uint32_t& lw) {
    uint32_t ua = __float_as_uint(a), ub = __float_as_uint(b);
    float ra = a - __uint_as_float(ua & 0xFFFF0000u);
    float rb = b - __uint_as_float(ub & 0xFFFF0000u);
    hw = __byte_perm(ua, ub, 0x7632);
    lw = __byte_perm(__float_as_uint(ra), __float_as_uint(rb), 0x7632);
}

// Scratch (device globals: allocation-free contract)
__device__ float g_kvfull[(size_t)ROWS * KVFD];
__device__ float g_qfull [(size_t)ROWS * QFD];
// Activation planes (bf16 hi/lo)
__device__ unsigned short g_xh    [(size_t)ROWS * DMODEL], g_xl    [(size_t)ROWS * DMODEL];
__device__ unsigned short g_kvlath[(size_t)ROWS * DLAT],   g_kvlatl[(size_t)ROWS * DLAT];
__device__ unsigned short g_qlath [(size_t)ROWS * DLAT],   g_qlatl [(size_t)ROWS * DLAT];
__device__ unsigned short g_ctxh  [(size_t)ROWS * DMODEL], g_ctxl  [(size_t)ROWS * DMODEL];
// Weight planes: transposed [N][K], split into bf16 hi/lo
__device__ unsigned short g_wkvd_h[(size_t)DLAT * DMODEL], g_wkvd_l[(size_t)DLAT * DMODEL];
__device__ unsigned short g_wqd_h [(size_t)DLAT * DMODEL], g_wqd_l [(size_t)DLAT * DMODEL];
__device__ unsigned short g_wkvu_h[(size_t)KVFD * DLAT],   g_wkvu_l[(size_t)KVFD * DLAT];
__device__ unsigned short g_wqu_h [(size_t)QFD  * DLAT],   g_wqu_l [(size_t)QFD  * DLAT];
__device__ unsigned short g_wo_h  [(size_t)DMODEL*DMODEL], g_wo_l  [(size_t)DMODEL*DMODEL];
// Attention operand planes (bf16 hi/lo), post-rope
__device__ unsigned short g_qh [(size_t)ROWS * (NH*DQK)], g_ql [(size_t)ROWS * (NH*DQK)];
__device__ unsigned short g_kh [(size_t)ROWS * (NH*DQK)], g_kl [(size_t)ROWS * (NH*DQK)];
__device__ unsigned short g_vth[(size_t)B_*NH*DH * S_],   g_vtl[(size_t)B_*NH*DH * S_];

// ---------------------------------------------------------------------------
// Transpose + bf16 split (weights): in [R][C] fp32 -> hi/lo [C][R] bf16.
// ---------------------------------------------------------------------------
__global__ __launch_bounds__(256) void transpose_split_kernel(
    const float* __restrict__ in, unsigned short* __restrict__ oh,
    unsigned short* __restrict__ ol, int R, int C)
{
    __shared__ float tile[32][33];
    int c0 = blockIdx.x * 32, r0 = blockIdx.y * 32;
    int tx = threadIdx.x, ty = threadIdx.y;
#pragma unroll
    for (int i = ty; i < 32; i += 8)
        tile[i][tx] = in[(size_t)(r0 + i) * C + c0 + tx];
    __syncthreads();
#pragma unroll
    for (int i = ty; i < 32; i += 8) {
        float v = tile[tx][i];
        uint32_t b = __float_as_uint(v);
        float res = v - __uint_as_float(b & 0xFFFF0000u);
        size_t o = (size_t)(c0 + i) * R + r0 + tx;
        oh[o] = (unsigned short)(b >> 16);
        ol[o] = (unsigned short)(__float_as_uint(res) >> 16);
    }
}

// ---------------------------------------------------------------------------
// Elementwise split: fp32 -> bf16 hi/lo planes (same layout). 4 elems/thread.
// ---------------------------------------------------------------------------
__global__ __launch_bounds__(256) void xsplit_kernel(
    const float* __restrict__ in, unsigned short* __restrict__ oh,
    unsigned short* __restrict__ ol)
{
    size_t f = (size_t)blockIdx.x * 256 + threadIdx.x;   // float4 index
    float4 v = *(const float4*)&in[f * 4];
    uint32_t h0, l0, h1, l1;
    split_pair(v.x, v.y, h0, l0);
    split_pair(v.z, v.w, h1, l1);
    ((uint2*)oh)[f] = make_uint2(h0, h1);
    ((uint2*)ol)[f] = make_uint2(l0, l1);
}

// ---------------------------------------------------------------------------
// HMMA split-bf16 GEMM, plane inputs: C = A @ Bt^T where A, Bt are bf16
// hi/lo plane pairs ([M][K] and [N][K]). Staging = pure uint4 copies
// (no split ALU in mainloop). Output: fp32 C, or hi/lo planes Ch/Cl.
// 128x128 tile, 256 thr, 8 warps (2x4), warp tile 64x32, K-chunk 16.
// ---------------------------------------------------------------------------
#define PSTR 12
#define PLW  (128 * PSTR)
#define STW  (4 * PLW)

__global__ __launch_bounds__(256) void hmma_gemm(
    const unsigned short* __restrict__ Ah, const unsigned short* __restrict__ Al,
    const unsigned short* __restrict__ Bh, const unsigned short* __restrict__ Bl,
    float* __restrict__ C, unsigned short* __restrict__ Ch,
    unsigned short* __restrict__ Cl, int M, int N, int K)
{
    __shared__ __align__(16) uint32_t smw[2 * STW];

    const int tid  = threadIdx.x;
    const int lane = tid & 31, wid = tid >> 5;
    const int g = lane >> 2, t = lane & 3;
    const int wm = wid >> 2, wn = wid & 3;
    const int bx = blockIdx.x, by = blockIdx.y;

    const unsigned short* Ahb = Ah + (size_t)by * 128 * K;
    const unsigned short* Alb = Al + (size_t)by * 128 * K;
    const unsigned short* Bhb = Bh + (size_t)bx * 128 * K;
    const unsigned short* Blb = Bl + (size_t)bx * 128 * K;

    float acc[4][4][4];
#pragma unroll
    for (int mt = 0; mt < 4; mt++)
#pragma unroll
        for (int nt = 0; nt < 4; nt++)
#pragma unroll
            for (int q = 0; q < 4; q++) acc[mt][nt][q] = 0.f;

    // staging map: row r2 (0..127), half hf — conflict-free uint4 STS
    const int r2 = tid & 127;
    const int hf = tid >> 7;
    const int sOff = r2 * PSTR + hf * 4;
    const size_t gOff = (size_t)r2 * K + hf * 8;

    // ldmatrix lane base addresses (stage 0); byte units
    const uint32_t sb0 = (uint32_t)__cvta_generic_to_shared(smw);
    const int arow0 = wm * 64 + (lane & 7) + ((lane >> 3) & 1) * 8;
    const uint32_t aAh = sb0 + (uint32_t)(arow0 * PSTR + (lane >> 4) * 4) * 4;
    const uint32_t aAl = aAh + PLW * 4;
    const int brow0 = wn * 32 + (lane & 7) + (lane >> 4) * 8;
    const uint32_t aBh = sb0 + (uint32_t)(2 * PLW + brow0 * PSTR + ((lane >> 3) & 1) * 4) * 4;
    const uint32_t aBl = aBh + PLW * 4;

    uint4 avh, avl, bvh, bvl;

    // ---- prologue: stage chunk 0 ----
    avh = *(const uint4*)&Ahb[gOff];
    avl = *(const uint4*)&Alb[gOff];
    bvh = *(const uint4*)&Bhb[gOff];
    bvl = *(const uint4*)&Blb[gOff];
    *(uint4*)&smw[sOff]           = avh;
    *(uint4*)&smw[PLW + sOff]     = avl;
    *(uint4*)&smw[2 * PLW + sOff] = bvh;
    *(uint4*)&smw[3 * PLW + sOff] = bvl;
    __syncthreads();

    const int NS = K / 16;
    for (int sI = 0; sI < NS; sI++) {
        const int cur = sI & 1;
        const bool more = (sI + 1) < NS;
        if (more) {
            const size_t go = gOff + (sI + 1) * 16;
            avh = *(const uint4*)&Ahb[go];
            avl = *(const uint4*)&Alb[go];
            bvh = *(const uint4*)&Bhb[go];
            bvl = *(const uint4*)&Blb[go];
        }

        // ---- compute on stage cur (ldmatrix fragments) ----
        {
            const uint32_t so = (uint32_t)cur * (STW * 4);

            uint32_t bfh[4][2], bfl[4][2];
            {
                uint32_t r[4];
                ldsm4(r, aBh + so);
                bfh[0][0] = r[0]; bfh[0][1] = r[1];
                bfh[1][0] = r[2]; bfh[1][1] = r[3];
                ldsm4(r, aBh + so + 16 * PSTR * 4);
                bfh[2][0] = r[0]; bfh[2][1] = r[1];
                bfh[3][0] = r[2]; bfh[3][1] = r[3];
                ldsm4(r, aBl + so);
                bfl[0][0] = r[0]; bfl[0][1] = r[1];
                bfl[1][0] = r[2]; bfl[1][1] = r[3];
                ldsm4(r, aBl + so + 16 * PSTR * 4);
                bfl[2][0] = r[0]; bfl[2][1] = r[1];
                bfl[3][0] = r[2]; bfl[3][1] = r[3];
            }
#pragma unroll
            for (int mt = 0; mt < 4; mt++) {
                uint32_t ah[4], al[4];
                ldsm4(ah, aAh + so + mt * (16 * PSTR * 4));
                ldsm4(al, aAl + so + mt * (16 * PSTR * 4));
#pragma unroll
                for (int nt = 0; nt < 4; nt++) {
                    mma_bf16(acc[mt][nt], ah, bfh[nt]);
                    mma_bf16(acc[mt][nt], ah, bfl[nt]);
                    mma_bf16(acc[mt][nt], al, bfh[nt]);
                }
            }
        }

        if (more) {
            uint32_t* st = smw + (cur ^ 1) * STW;
            *(uint4*)&st[sOff]           = avh;
            *(uint4*)&st[PLW + sOff]     = avl;
            *(uint4*)&st[2 * PLW + sOff] = bvh;
            *(uint4*)&st[3 * PLW + sOff] = bvl;
        }
        __syncthreads();
    }

    // ---- epilogue: fp32 or split-plane output ----
    if (C != nullptr) {
#pragma unroll
        for (int mt = 0; mt < 4; mt++) {
            int row = by * 128 + wm * 64 + mt * 16 + g;
#pragma unroll
            for (int nt = 0; nt < 4; nt++) {
                int col = bx * 128 + wn * 32 + nt * 8 + 2 * t;
                *(float2*)&C[(size_t)row * N + col]       = make_float2(acc[mt][nt][0], acc[mt][nt][1]);
                *(float2*)&C[(size_t)(row + 8) * N + col] = make_float2(acc[mt][nt][2], acc[mt][nt][3]);
            }
        }
    } else {
#pragma unroll
        for (int mt = 0; mt < 4; mt++) {
            int row = by * 128 + wm * 64 + mt * 16 + g;
#pragma unroll
            for (int nt = 0; nt < 4; nt++) {
                int col = bx * 128 + wn * 32 + nt * 8 + 2 * t;
                uint32_t hw, lw;
                split_pair(acc[mt][nt][0], acc[mt][nt][1], hw, lw);
                ((uint32_t*)Ch)[((size_t)row * N + col) >> 1] = hw;
                ((uint32_t*)Cl)[((size_t)row * N + col) >> 1] = lw;
                split_pair(acc[mt][nt][2], acc[mt][nt][3], hw, lw);
                ((uint32_t*)Ch)[((size_t)(row + 8) * N + col) >> 1] = hw;
                ((uint32_t*)Cl)[((size_t)(row + 8) * N + col) >> 1] = lw;
            }
        }
    }
}

// ---------------------------------------------------------------------------
// RoPE helper: float4 at dim c (>=128) of a 192-dim q/k head vector.
// ---------------------------------------------------------------------------
__device__ __forceinline__ float4 rope4(float4 v, float4 p, int c, int s) {
    int j = c - 128;
    bool first = (j < 32);
    int jb = first ? j : (j - 32);
    float4 r;
#pragma unroll
    for (int e = 0; e < 4; e++) {
        float inv = __expf(-(float)(jb + e) * (9.210340371976184f / 32.f));
        float ang = (float)s * inv;
        float cs, sn;
        __sincosf(ang, &sn, &cs);
        float ve = (e == 0) ? v.x : (e == 1) ? v.y : (e == 2) ? v.z : v.w;
        float pe = (e == 0) ? p.x : (e == 1) ? p.y : (e == 2) ? p.z : p.w;
        float o = first ? (ve * cs - pe * sn) : (ve * cs + pe * sn);
        if (e == 0) r.x = o; else if (e == 1) r.y = o; else if (e == 2) r.z = o; else r.w = o;
    }
    return r;
}

// Q: rope + scale + split, g_qfull -> g_qh/g_ql (same layout)
__global__ __launch_bounds__(256) void qsplit_kernel()
{
    const float scale = 0.07216878364870323f;   // 1/sqrt(192)
    size_t f = (size_t)blockIdx.x * 256 + threadIdx.x;   // float4 index
    int w = (int)(f % 768);
    int c = (w % 48) * 4;
    int row = (int)(f / 768);
    int s = row & (S_ - 1);
    float4 v = *(const float4*)&g_qfull[f * 4];
    if (c >= 128) {
        float4 p = (c < 160) ? *(const float4*)&g_qfull[f * 4 + 32]
                             : *(const float4*)&g_qfull[f * 4 - 32];
        v = rope4(v, p, c, s);
    }
    v.x *= scale; v.y *= scale; v.z *= scale; v.w *= scale;
    uint32_t h0, l0, h1, l1;
    split_pair(v.x, v.y, h0, l0);
    split_pair(v.z, v.w, h1, l1);
    ((uint2*)g_qh)[f] = make_uint2(h0, h1);
    ((uint2*)g_ql)[f] = make_uint2(l0, l1);
}

// K: rope + split, g_kvfull K-slice -> g_kh/g_kl [row][h*192+c]
__global__ __launch_bounds__(256) void ksplit_kernel()
{
    size_t f = (size_t)blockIdx.x * 256 + threadIdx.x;   // unit = 4 floats
    int c4 = (int)(f % 48);
    int h  = (int)((f / 48) % NH);
    int row = (int)(f / 768);
    int s = row & (S_ - 1);
    int c = c4 * 4;
    size_t base = (size_t)row * KVFD + h * KVD + c;
    float4 v = *(const float4*)&g_kvfull[base];
    if (c >= 128) {
        float4 p = (c < 160) ? *(const float4*)&g_kvfull[base + 32]
                             : *(const float4*)&g_kvfull[base - 32];
        v = rope4(v, p, c, s);
    }
    uint32_t h0, l0, h1, l1;
    split_pair(v.x, v.y, h0, l0);
    split_pair(v.z, v.w, h1, l1);
    size_t o = ((size_t)row * (NH*DQK) + h * DQK + c) >> 2;
    ((uint2*)g_kh)[o] = make_uint2(h0, h1);
    ((uint2*)g_kl)[o] = make_uint2(l0, l1);
}

// V transpose+split: g_kvfull V-slice [s][d] -> g_vth/g_vtl [bh][d][s]
__global__ __launch_bounds__(256) void vtsplit_kernel()
{
    __shared__ float tile[32][33];
    int s0 = blockIdx.x * 32, d0 = blockIdx.y * 32, bh = blockIdx.z;
    int b = bh >> 4, h = bh & 15;
    int tx = threadIdx.x, ty = threadIdx.y;
#pragma unroll
    for (int i = ty; i < 32; i += 8)
        tile[i][tx] = g_kvfull[(size_t)(b * S_ + s0 + i) * KVFD + h * KVD + DH + DR + d0 + tx];
    __syncthreads();
#pragma unroll
    for (int i = ty; i < 32; i += 8) {
        float v = tile[tx][i];
        uint32_t bbits = __float_as_uint(v);
        float res = v - __uint_as_float(bbits & 0xFFFF0000u);
        size_t o = ((size_t)bh * DH + d0 + i) * S_ + s0 + tx;
        g_vth[o] = (unsigned short)(bbits >> 16);
        g_vtl[o] = (unsigned short)(__float_as_uint(res) >> 16);
    }
}

// ---------------------------------------------------------------------------
// HMMA flash attention (causal): BM=128, BN=64, 8 warps (16 q-rows each).
// Split-bf16 3-term QK and PV; P stays in registers. Output: ctx planes.
// ---------------------------------------------------------------------------
#define QW 100                 // Q/K smem row stride in words (== 4 mod 32)
#define VW 36                  // VT smem row stride in words  (== 4 mod 32)
#define SM_QH  0
#define SM_QL  12800
#define SM_KH  25600
#define SM_KL  32000
#define SM_VTH 38400
#define SM_VTL 43008
#define ATTN_SMEM_BYTES (47616 * 4)    // 190,464 B

__global__ __launch_bounds__(256, 1) void attn_mma_kernel()
{
    extern __shared__ uint32_t smw[];
    const int qt  = gridDim.x - 1 - blockIdx.x;   // long blocks first
    const int h   = blockIdx.y;
    const int b   = blockIdx.z;
    const int tid = threadIdx.x;
    const int lane = tid & 31, wid = tid >> 5;
    const int g = lane >> 2, t = lane & 3;
    const int qs0 = qt * 128;
    const int mr  = wid * 16;
    const int bh  = b * NH + h;

    const uint32_t sbase = (uint32_t)__cvta_generic_to_shared(smw);
    const uint32_t aQh = sbase + (SM_QH + (mr + (lane & 15)) * QW + ((lane >> 4) << 2)) * 4;
    const uint32_t aQl = aQh + (SM_QL - SM_QH) * 4;
    const int      bRow = (lane & 7) + ((lane >> 4) & 1) * 8;
    const uint32_t bWrd = ((lane >> 3) & 1) * 4;
    const uint32_t aKh = sbase + (SM_KH + bRow * QW + bWrd) * 4;
    const uint32_t aKl = aKh + (SM_KL - SM_KH) * 4;
    const uint32_t aVh = sbase + (SM_VTH + bRow * VW + bWrd) * 4;
    const uint32_t aVl = aVh + (SM_VTL - SM_VTH) * 4;

    // Stage Q (hi/lo): 128 rows x 24 uint4 per plane
    {
        const uint4* qh = (const uint4*)(g_qh + (size_t)(b * S_ + qs0) * (NH*DQK) + h * DQK);
        const uint4* ql = (const uint4*)(g_ql + (size_t)(b * S_ + qs0) * (NH*DQK) + h * DQK);
        for (int f = tid; f < 128 * 24; f += 256) {
            int r = f / 24, w = f % 24;
            *(uint4*)(smw + SM_QH + r * QW + w * 4) = qh[(size_t)r * 384 + w];
            *(uint4*)(smw + SM_QL + r * QW + w * 4) = ql[(size_t)r * 384 + w];
        }
    }

    float m0 = -1e30f, m1 = -1e30f, l0 = 0.f, l1 = 0.f;
    float o[16][4];
#pragma unroll
    for (int nt = 0; nt < 16; nt++)
#pragma unroll
        for (int e = 0; e < 4; e++) o[nt][e] = 0.f;

    for (int kt = 0; kt <= qs0 + 64; kt += 64) {
        __syncthreads();
        {
            const uint4* kh = (const uint4*)(g_kh + (size_t)(b * S_ + kt) * (NH*DQK) + h * DQK);
            const uint4* kl = (const uint4*)(g_kl + (size_t)(b * S_ + kt) * (NH*DQK) + h * DQK);
            for (int f = tid; f < 64 * 24; f += 256) {
                int r = f / 24, w = f % 24;
                *(uint4*)(smw + SM_KH + r * QW + w * 4) = kh[(size_t)r * 384 + w];
                *(uint4*)(smw + SM_KL + r * QW + w * 4) = kl[(size_t)r * 384 + w];
            }
        }
        {
            for (int f = tid; f < 128 * 8; f += 256) {
                int d = f / 8, w = f % 8;
                const uint4* vh = (const uint4*)(g_vth + ((size_t)bh * DH + d) * S_ + kt);
                const uint4* vl = (const uint4*)(g_vtl + ((size_t)bh * DH + d) * S_ + kt);
                *(uint4*)(smw + SM_VTH + d * VW + w * 4) = vh[w];
                *(uint4*)(smw + SM_VTL + d * VW + w * 4) = vl[w];
            }
        }
        __syncthreads();

        if (kt > qs0 + mr + 15) continue;   // warp tile fully masked (warp-uniform)

        // ---- QK: S = Q K^T, 3-term split ----
        float s[8][4];
#pragma unroll
        for (int nt = 0; nt < 8; nt++)
#pragma unroll
            for (int e = 0; e < 4; e++) s[nt][e] = 0.f;

#pragma unroll
        for (int c = 0; c < 12; c++) {
            uint32_t ah[4], al[4];
            ldsm4(ah, aQh + c * 32);
            ldsm4(al, aQl + c * 32);
#pragma unroll
            for (int q = 0; q < 4; q++) {
                uint32_t kh[4], kl[4];
                ldsm4(kh, aKh + q * (16 * QW * 4) + c * 32);
                ldsm4(kl, aKl + q * (16 * QW * 4) + c * 32);
                mma_bf16(s[2*q],   ah, kh);     mma_bf16(s[2*q],   ah, kl);
                mma_bf16(s[2*q],   al, kh);
                mma_bf16(s[2*q+1], ah, kh + 2); mma_bf16(s[2*q+1], ah, kl + 2);
                mma_bf16(s[2*q+1], al, kh + 2);
            }
        }

        // causal mask (diagonal-straddling tiles only)
        if (kt >= qs0) {
            int r0 = qs0 + mr + g, r1 = r0 + 8;
#pragma unroll
            for (int nt = 0; nt < 8; nt++) {
                int c0 = kt + nt * 8 + 2 * t;
                if (c0 > r0)     s[nt][0] = -1e30f;
                if (c0 + 1 > r0) s[nt][1] = -1e30f;
                if (c0 > r1)     s[nt][2] = -1e30f;
                if (c0 + 1 > r1) s[nt][3] = -1e30f;
            }
        }

        // ---- online softmax on fragments ----
        float rm0 = -1e30f, rm1 = -1e30f;
#pragma unroll
        for (int nt = 0; nt < 8; nt++) {
            rm0 = fmaxf(rm0, fmaxf(s[nt][0], s[nt][1]));
            rm1 = fmaxf(rm1, fmaxf(s[nt][2], s[nt][3]));
        }
        rm0 = fmaxf(rm0, __shfl_xor_sync(0xffffffffu, rm0, 1));
        rm0 = fmaxf(rm0, __shfl_xor_sync(0xffffffffu, rm0, 2));
        rm1 = fmaxf(rm1, __shfl_xor_sync(0xffffffffu, rm1, 1));
        rm1 = fmaxf(rm1, __shfl_xor_sync(0xffffffffu, rm1, 2));
        float mn0 = fmaxf(m0, rm0), mn1 = fmaxf(m1, rm1);
        float corr0 = __expf(m0 - mn0), corr1 = __expf(m1 - mn1);
        m0 = mn0; m1 = mn1;

        float rs0 = 0.f, rs1 = 0.f;
#pragma unroll
        for (int nt = 0; nt < 8; nt++) {
            s[nt][0] = __expf(s[nt][0] - mn0);
            s[nt][1] = __expf(s[nt][1] - mn0);
            s[nt][2] = __expf(s[nt][2] - mn1);
            s[nt][3] = __expf(s[nt][3] - mn1);
            rs0 += s[nt][0] + s[nt][1];
            rs1 += s[nt][2] + s[nt][3];
        }
        rs0 += __shfl_xor_sync(0xffffffffu, rs0, 1);
        rs0 += __shfl_xor_sync(0xffffffffu, rs0, 2);
        rs1 += __shfl_xor_sync(0xffffffffu, rs1, 1);
        rs1 += __shfl_xor_sync(0xffffffffu, rs1, 2);
        l0 = l0 * corr0 + rs0;
        l1 = l1 * corr1 + rs1;

#pragma unroll
        for (int nt = 0; nt < 16; nt++) {
            o[nt][0] *= corr0; o[nt][1] *= corr0;
            o[nt][2] *= corr1; o[nt][3] *= corr1;
        }

        // ---- pack P into split bf16 A-fragments (registers only) ----
        uint32_t php[8][2], plp[8][2];
#pragma unroll
        for (int nt = 0; nt < 8; nt++) {
            split_pair(s[nt][0], s[nt][1], php[nt][0], plp[nt][0]);
            split_pair(s[nt][2], s[nt][3], php[nt][1], plp[nt][1]);
        }

        // ---- PV: O += P V, 3-term split ----
#pragma unroll
        for (int kc = 0; kc < 4; kc++) {
            uint32_t pah[4] = {php[2*kc][0], php[2*kc][1], php[2*kc+1][0], php[2*kc+1][1]};
            uint32_t pal[4] = {plp[2*kc][0], plp[2*kc][1], plp[2*kc+1][0], plp[2*kc+1][1]};
#pragma unroll
            for (int vq = 0; vq < 8; vq++) {
                uint32_t vh[4], vl[4];
                ldsm4(vh, aVh + vq * (16 * VW * 4) + kc * 32);
                ldsm4(vl, aVl + vq * (16 * VW * 4) + kc * 32);
                mma_bf16(o[2*vq],   pah, vh);     mma_bf16(o[2*vq],   pah, vl);
                mma_bf16(o[2*vq],   pal, vh);
                mma_bf16(o[2*vq+1], pah, vh + 2); mma_bf16(o[2*vq+1], pah, vl + 2);
                mma_bf16(o[2*vq+1], pal, vh + 2);
            }
        }
    }

    // ---- finalize + store ctx as bf16 hi/lo planes ----
    float inv0 = 1.f / l0, inv1 = 1.f / l1;
    int row0 = b * S_ + qs0 + mr + g;
#pragma unroll
    for (int nt = 0; nt < 16; nt++) {
        int col = h * DH + nt * 8 + 2 * t;
        uint32_t hw, lw;
        split_pair(o[nt][0] * inv0, o[nt][1] * inv0, hw, lw);
        ((uint32_t*)g_ctxh)[((size_t)row0 * DMODEL + col) >> 1] = hw;
        ((uint32_t*)g_ctxl)[((size_t)row0 * DMODEL + col) >> 1] = lw;
        split_pair(o[nt][2] * inv1, o[nt][3] * inv1, hw, lw);
        ((uint32_t*)g_ctxh)[((size_t)(row0 + 8) * DMODEL + col) >> 1] = hw;
        ((uint32_t*)g_ctxl)[((size_t)(row0 + 8) * DMODEL + col) >> 1] = lw;
    }
}

// ---------------------------------------------------------------------------
// Launch
// ---------------------------------------------------------------------------
extern "C" void kernel_launch(void* const* d_in, const int* in_sizes, int n_in,
                              void* d_out, int out_size)
{
    (void)in_sizes; (void)n_in; (void)out_size;
    const float* x    = (const float*)d_in[0];
    const float* Wkvd = (const float*)d_in[1];
    const float* Wkvu = (const float*)d_in[2];
    const float* Wqd  = (const float*)d_in[3];
    const float* Wqu  = (const float*)d_in[4];
    const float* Wo   = (const float*)d_in[5];
    float* out = (float*)d_out;

    float *kvfull, *qfull;
    unsigned short *xh, *xl, *kvlath, *kvlatl, *qlath, *qlatl, *ctxh, *ctxl;
    unsigned short *wkvdH, *wkvdL, *wqdH, *wqdL, *wkvuH, *wkvuL, *wquH, *wquL, *woH, *woL;
    cudaGetSymbolAddress((void**)&kvfull, g_kvfull);
    cudaGetSymbolAddress((void**)&qfull,  g_qfull);
    cudaGetSymbolAddress((void**)&xh,     g_xh);
    cudaGetSymbolAddress((void**)&xl,     g_xl);
    cudaGetSymbolAddress((void**)&kvlath, g_kvlath);
    cudaGetSymbolAddress((void**)&kvlatl, g_kvlatl);
    cudaGetSymbolAddress((void**)&qlath,  g_qlath);
    cudaGetSymbolAddress((void**)&qlatl,  g_qlatl);
    cudaGetSymbolAddress((void**)&ctxh,   g_ctxh);
    cudaGetSymbolAddress((void**)&ctxl,   g_ctxl);
    cudaGetSymbolAddress((void**)&wkvdH,  g_wkvd_h);
    cudaGetSymbolAddress((void**)&wkvdL,  g_wkvd_l);
    cudaGetSymbolAddress((void**)&wqdH,   g_wqd_h);
    cudaGetSymbolAddress((void**)&wqdL,   g_wqd_l);
    cudaGetSymbolAddress((void**)&wkvuH,  g_wkvu_h);
    cudaGetSymbolAddress((void**)&wkvuL,  g_wkvu_l);
    cudaGetSymbolAddress((void**)&wquH,   g_wqu_h);
    cudaGetSymbolAddress((void**)&wquL,   g_wqu_l);
    cudaGetSymbolAddress((void**)&woH,    g_wo_h);
    cudaGetSymbolAddress((void**)&woL,    g_wo_l);

    dim3 tt(32, 8);
    transpose_split_kernel<<<dim3(DLAT / 32, DMODEL / 32), tt>>>(Wkvd, wkvdH, wkvdL, DMODEL, DLAT);
    transpose_split_kernel<<<dim3(DLAT / 32, DMODEL / 32), tt>>>(Wqd,  wqdH,  wqdL,  DMODEL, DLAT);
    transpose_split_kernel<<<dim3(KVFD / 32, DLAT / 32),   tt>>>(Wkvu, wkvuH, wkvuL, DLAT,  KVFD);
    transpose_split_kernel<<<dim3(QFD  / 32, DLAT / 32),   tt>>>(Wqu,  wquH,  wquL,  DLAT,  QFD);
    transpose_split_kernel<<<dim3(DMODEL / 32, DMODEL / 32), tt>>>(Wo, woH,   woL,   DMODEL, DMODEL);

    // split x once
    xsplit_kernel<<<(ROWS * (size_t)DMODEL / 4) / 256, 256>>>(x, xh, xl);

    dim3 t(256);
    // down-projections: plane in, plane out (no fp32 intermediates)
    hmma_gemm<<<dim3(DLAT / 128, ROWS / 128), t>>>(xh, xl, wkvdH, wkvdL,
                                                   nullptr, kvlath, kvlatl, ROWS, DLAT, DMODEL);
    hmma_gemm<<<dim3(DLAT / 128, ROWS / 128), t>>>(xh, xl, wqdH, wqdL,
                                                   nullptr, qlath, qlatl, ROWS, DLAT, DMODEL);
    // up-projections: plane in, fp32 out (rope splits need positional reads)
    hmma_gemm<<<dim3(KVFD / 128, ROWS / 128), t>>>(kvlath, kvlatl, wkvuH, wkvuL,
                                                   kvfull, nullptr, nullptr, ROWS, KVFD, DLAT);
    hmma_gemm<<<dim3(QFD  / 128, ROWS / 128), t>>>(qlath, qlatl, wquH, wquL,
                                                   qfull, nullptr, nullptr, ROWS, QFD, DLAT);

    // rope + split into attention planes
    qsplit_kernel<<<(ROWS * (size_t)QFD / 4) / 256, 256>>>();
    ksplit_kernel<<<(ROWS * (size_t)NH * 48) / 256, 256>>>();
    vtsplit_kernel<<<dim3(S_ / 32, DH / 32, B_ * NH), tt>>>();

    cudaFuncSetAttribute(attn_mma_kernel, cudaFuncAttributeMaxDynamicSharedMemorySize, ATTN_SMEM_BYTES);
    attn_mma_kernel<<<dim3(S_ / 128, NH, B_), 256, ATTN_SMEM_BYTES>>>();

    // output projection: ctx planes in, fp32 out
    hmma_gemm<<<dim3(DMODEL / 128, ROWS / 128), t>>>(ctxh, ctxl, woH, woL,
                                                     out, nullptr, nullptr, ROWS, DMODEL, DMODEL);
}

// round 15
// speedup vs baseline: 1.3379x; 1.3379x over previous
#include <cuda_runtime.h>
#include <cuda_bf16.h>
#include <math.h>
#include <stdint.h>

// Problem constants
#define B_      2
#define S_      2048
#define DMODEL  2048
#define NH      16
#define DH      128
#define DLAT    512
#define DR      64
#define DQK     192            // DH + DR
#define KVD     320            // DH + DR + DH
#define QFD     3072           // NH * DQK
#define KVFD    5120           // NH * KVD
#define ROWS    (B_*S_)        // 4096

// ---- warp-level bf16 MMA (sm_80+, works at compute_100) ----
__device__ __forceinline__ void mma_bf16(float* c, const uint32_t* a, const uint32_t* b) {
    asm("mma.sync.aligned.m16n8k16.row.col.f32.bf16.bf16.f32 "
        "{%0,%1,%2,%3}, {%4,%5,%6,%7}, {%8,%9}, {%0,%1,%2,%3};"
        : "+f"(c[0]), "+f"(c[1]), "+f"(c[2]), "+f"(c[3])
        : "r"(a[0]), "r"(a[1]), "r"(a[2]), "r"(a[3]), "r"(b[0]), "r"(b[1]));
}
__device__ __forceinline__ void ldsm4(uint32_t* r, uint32_t a) {
    asm volatile("ldmatrix.sync.aligned.m8n8.x4.shared.b16 {%0,%1,%2,%3}, [%4];"
        : "=r"(r[0]), "=r"(r[1]), "=r"(r[2]), "=r"(r[3]) : "r"(a));
}

// ---- split helper: fp32 pair -> bf16 hi/lo words ----
__device__ __forceinline__ void split_pair(float a, float b, uint32_t& hw, uint32_t& lw) {
    uint32_t ua = __float_as_uint(a), ub = __float_as_uint(b);
    float ra = a - __uint_as_float(ua & 0xFFFF0000u);
    float rb = b - __uint_as_float(ub & 0xFFFF0000u);
    hw = __byte_perm(ua, ub, 0x7632);
    lw = __byte_perm(__float_as_uint(ra), __float_as_uint(rb), 0x7632);
}

// Scratch (device globals: allocation-free contract)
__device__ float g_kvfull[(size_t)ROWS * KVFD];
__device__ float g_qfull [(size_t)ROWS * QFD];
// Activation planes (bf16 hi/lo)
__device__ unsigned short g_xh    [(size_t)ROWS * DMODEL], g_xl    [(size_t)ROWS * DMODEL];
__device__ unsigned short g_kvlath[(size_t)ROWS * DLAT],   g_kvlatl[(size_t)ROWS * DLAT];
__device__ unsigned short g_qlath [(size_t)ROWS * DLAT],   g_qlatl [(size_t)ROWS * DLAT];
__device__ unsigned short g_ctxh  [(size_t)ROWS * DMODEL], g_ctxl  [(size_t)ROWS * DMODEL];
// Weight planes: transposed [N][K], split into bf16 hi/lo
__device__ unsigned short g_wkvd_h[(size_t)DLAT * DMODEL], g_wkvd_l[(size_t)DLAT * DMODEL];
__device__ unsigned short g_wqd_h [(size_t)DLAT * DMODEL], g_wqd_l [(size_t)DLAT * DMODEL];
__device__ unsigned short g_wkvu_h[(size_t)KVFD * DLAT],   g_wkvu_l[(size_t)KVFD * DLAT];
__device__ unsigned short g_wqu_h [(size_t)QFD  * DLAT],   g_wqu_l [(size_t)QFD  * DLAT];
__device__ unsigned short g_wo_h  [(size_t)DMODEL*DMODEL], g_wo_l  [(size_t)DMODEL*DMODEL];
// Attention operand planes (bf16 hi/lo), post-rope
__device__ unsigned short g_qh [(size_t)ROWS * (NH*DQK)], g_ql [(size_t)ROWS * (NH*DQK)];
__device__ unsigned short g_kh [(size_t)ROWS * (NH*DQK)], g_kl [(size_t)ROWS * (NH*DQK)];
__device__ unsigned short g_vth[(size_t)B_*NH*DH * S_],   g_vtl[(size_t)B_*NH*DH * S_];

// ---------------------------------------------------------------------------
// Transpose + bf16 split (weights): in [R][C] fp32 -> hi/lo [C][R] bf16.
// ---------------------------------------------------------------------------
__global__ __launch_bounds__(256) void transpose_split_kernel(
    const float* __restrict__ in, unsigned short* __restrict__ oh,
    unsigned short* __restrict__ ol, int R, int C)
{
    __shared__ float tile[32][33];
    int c0 = blockIdx.x * 32, r0 = blockIdx.y * 32;
    int tx = threadIdx.x, ty = threadIdx.y;
#pragma unroll
    for (int i = ty; i < 32; i += 8)
        tile[i][tx] = in[(size_t)(r0 + i) * C + c0 + tx];
    __syncthreads();
#pragma unroll
    for (int i = ty; i < 32; i += 8) {
        float v = tile[tx][i];
        uint32_t b = __float_as_uint(v);
        float res = v - __uint_as_float(b & 0xFFFF0000u);
        size_t o = (size_t)(c0 + i) * R + r0 + tx;
        oh[o] = (unsigned short)(b >> 16);
        ol[o] = (unsigned short)(__float_as_uint(res) >> 16);
    }
}

// ---------------------------------------------------------------------------
// Elementwise split: fp32 -> bf16 hi/lo planes (same layout). 4 elems/thread.
// ---------------------------------------------------------------------------
__global__ __launch_bounds__(256) void xsplit_kernel(
    const float* __restrict__ in, unsigned short* __restrict__ oh,
    unsigned short* __restrict__ ol)
{
    size_t f = (size_t)blockIdx.x * 256 + threadIdx.x;   // float4 index
    float4 v = *(const float4*)&in[f * 4];
    uint32_t h0, l0, h1, l1;
    split_pair(v.x, v.y, h0, l0);
    split_pair(v.z, v.w, h1, l1);
    ((uint2*)oh)[f] = make_uint2(h0, h1);
    ((uint2*)ol)[f] = make_uint2(l0, l1);
}

// ---------------------------------------------------------------------------
// HMMA split-bf16 GEMM, plane inputs, K-chunk 32 (coalesced staging):
// C = A @ Bt^T; A, Bt are bf16 hi/lo plane pairs ([M][K], [N][K]).
// Staging: per k32 stage each quad loads 64B contiguous per row (8 lines/warp).
// 128x128 tile, 256 thr, 8 warps (2x4), warp tile 64x32, 80KB dynamic smem.
// ---------------------------------------------------------------------------
#define PSTR 20                // words per 32-bf16 row (16 data + 4 pad)
#define PLW  (128 * PSTR)
#define STW  (4 * PLW)         // Ah, Al, Bh, Bl
#define GEMM_SMEM_BYTES (2 * STW * 4)   // 81,920 B

__global__ __launch_bounds__(256, 1) void hmma_gemm(
    const unsigned short* __restrict__ Ah, const unsigned short* __restrict__ Al,
    const unsigned short* __restrict__ Bh, const unsigned short* __restrict__ Bl,
    float* __restrict__ C, unsigned short* __restrict__ Ch,
    unsigned short* __restrict__ Cl, int M, int N, int K)
{
    extern __shared__ uint32_t smw[];

    const int tid  = threadIdx.x;
    const int lane = tid & 31, wid = tid >> 5;
    const int g = lane >> 2, t = lane & 3;
    const int wm = wid >> 2, wn = wid & 3;
    const int bx = blockIdx.x, by = blockIdx.y;

    const unsigned short* Ahb = Ah + (size_t)by * 128 * K;
    const unsigned short* Alb = Al + (size_t)by * 128 * K;
    const unsigned short* Bhb = Bh + (size_t)bx * 128 * K;
    const unsigned short* Blb = Bl + (size_t)bx * 128 * K;

    float acc[4][4][4];
#pragma unroll
    for (int mt = 0; mt < 4; mt++)
#pragma unroll
        for (int nt = 0; nt < 4; nt++)
#pragma unroll
            for (int q = 0; q < 4; q++) acc[mt][nt][q] = 0.f;

    // staging map: quad covers 64B of one row; rows r and r+64 per thread
    const int r0s = tid >> 2;          // 0..63
    const int c4  = tid & 3;           // 16B unit within 64B row-chunk
    const int sOff0 = r0s * PSTR + c4 * 4;
    const int sOff1 = (r0s + 64) * PSTR + c4 * 4;
    const size_t gOff0 = (size_t)r0s * K + c4 * 8;          // ushort units
    const size_t gOff1 = (size_t)(r0s + 64) * K + c4 * 8;

    // ldmatrix lane base addresses (stage 0); byte units
    const uint32_t sb0 = (uint32_t)__cvta_generic_to_shared(smw);
    const int arow0 = wm * 64 + (lane & 7) + ((lane >> 3) & 1) * 8;
    const uint32_t aAh = sb0 + (uint32_t)(arow0 * PSTR + (lane >> 4) * 4) * 4;
    const uint32_t aAl = aAh + PLW * 4;
    const int brow0 = wn * 32 + (lane & 7) + (lane >> 4) * 8;
    const uint32_t aBh = sb0 + (uint32_t)(2 * PLW + brow0 * PSTR + ((lane >> 3) & 1) * 4) * 4;
    const uint32_t aBl = aBh + PLW * 4;

    uint4 avh0, avh1, avl0, avl1, bvh0, bvh1, bvl0, bvl1;

    // ---- prologue: stage k32-chunk 0 ----
    avh0 = *(const uint4*)&Ahb[gOff0];  avh1 = *(const uint4*)&Ahb[gOff1];
    avl0 = *(const uint4*)&Alb[gOff0];  avl1 = *(const uint4*)&Alb[gOff1];
    bvh0 = *(const uint4*)&Bhb[gOff0];  bvh1 = *(const uint4*)&Bhb[gOff1];
    bvl0 = *(const uint4*)&Blb[gOff0];  bvl1 = *(const uint4*)&Blb[gOff1];
    *(uint4*)&smw[sOff0]           = avh0;  *(uint4*)&smw[sOff1]           = avh1;
    *(uint4*)&smw[PLW + sOff0]     = avl0;  *(uint4*)&smw[PLW + sOff1]     = avl1;
    *(uint4*)&smw[2 * PLW + sOff0] = bvh0;  *(uint4*)&smw[2 * PLW + sOff1] = bvh1;
    *(uint4*)&smw[3 * PLW + sOff0] = bvl0;  *(uint4*)&smw[3 * PLW + sOff1] = bvl1;
    __syncthreads();

    const int NS = K / 32;
    for (int sI = 0; sI < NS; sI++) {
        const int cur = sI & 1;
        const bool more = (sI + 1) < NS;
        if (more) {
            const size_t go = (size_t)(sI + 1) * 32;
            avh0 = *(const uint4*)&Ahb[gOff0 + go];  avh1 = *(const uint4*)&Ahb[gOff1 + go];
            avl0 = *(const uint4*)&Alb[gOff0 + go];  avl1 = *(const uint4*)&Alb[gOff1 + go];
            bvh0 = *(const uint4*)&Bhb[gOff0 + go];  bvh1 = *(const uint4*)&Bhb[gOff1 + go];
            bvl0 = *(const uint4*)&Blb[gOff0 + go];  bvl1 = *(const uint4*)&Blb[gOff1 + go];
        }

        // ---- compute: 2 k16 sub-chunks on stage cur ----
        const uint32_t stg = (uint32_t)cur * (STW * 4);
#pragma unroll
        for (int sub = 0; sub < 2; sub++) {
            const uint32_t so = stg + sub * 32;   // 16 bf16 = 32 bytes

            uint32_t bfh[4][2], bfl[4][2];
            {
                uint32_t r[4];
                ldsm4(r, aBh + so);
                bfh[0][0] = r[0]; bfh[0][1] = r[1];
                bfh[1][0] = r[2]; bfh[1][1] = r[3];
                ldsm4(r, aBh + so + 16 * PSTR * 4);
                bfh[2][0] = r[0]; bfh[2][1] = r[1];
                bfh[3][0] = r[2]; bfh[3][1] = r[3];
                ldsm4(r, aBl + so);
                bfl[0][0] = r[0]; bfl[0][1] = r[1];
                bfl[1][0] = r[2]; bfl[1][1] = r[3];
                ldsm4(r, aBl + so + 16 * PSTR * 4);
                bfl[2][0] = r[0]; bfl[2][1] = r[1];
                bfl[3][0] = r[2]; bfl[3][1] = r[3];
            }
#pragma unroll
            for (int mt = 0; mt < 4; mt++) {
                uint32_t ah[4], al[4];
                ldsm4(ah, aAh + so + mt * (16 * PSTR * 4));
                ldsm4(al, aAl + so + mt * (16 * PSTR * 4));
#pragma unroll
                for (int nt = 0; nt < 4; nt++) {
                    mma_bf16(acc[mt][nt], ah, bfh[nt]);
                    mma_bf16(acc[mt][nt], ah, bfl[nt]);
                    mma_bf16(acc[mt][nt], al, bfh[nt]);
                }
            }
        }

        if (more) {
            uint32_t* st = smw + (cur ^ 1) * STW;
            *(uint4*)&st[sOff0]           = avh0;  *(uint4*)&st[sOff1]           = avh1;
            *(uint4*)&st[PLW + sOff0]     = avl0;  *(uint4*)&st[PLW + sOff1]     = avl1;
            *(uint4*)&st[2 * PLW + sOff0] = bvh0;  *(uint4*)&st[2 * PLW + sOff1] = bvh1;
            *(uint4*)&st[3 * PLW + sOff0] = bvl0;  *(uint4*)&st[3 * PLW + sOff1] = bvl1;
        }
        __syncthreads();
    }

    // ---- epilogue: fp32 or split-plane output ----
    if (C != nullptr) {
#pragma unroll
        for (int mt = 0; mt < 4; mt++) {
            int row = by * 128 + wm * 64 + mt * 16 + g;
#pragma unroll
            for (int nt = 0; nt < 4; nt++) {
                int col = bx * 128 + wn * 32 + nt * 8 + 2 * t;
                *(float2*)&C[(size_t)row * N + col]       = make_float2(acc[mt][nt][0], acc[mt][nt][1]);
                *(float2*)&C[(size_t)(row + 8) * N + col] = make_float2(acc[mt][nt][2], acc[mt][nt][3]);
            }
        }
    } else {
#pragma unroll
        for (int mt = 0; mt < 4; mt++) {
            int row = by * 128 + wm * 64 + mt * 16 + g;
#pragma unroll
            for (int nt = 0; nt < 4; nt++) {
                int col = bx * 128 + wn * 32 + nt * 8 + 2 * t;
                uint32_t hw, lw;
                split_pair(acc[mt][nt][0], acc[mt][nt][1], hw, lw);
                ((uint32_t*)Ch)[((size_t)row * N + col) >> 1] = hw;
                ((uint32_t*)Cl)[((size_t)row * N + col) >> 1] = lw;
                split_pair(acc[mt][nt][2], acc[mt][nt][3], hw, lw);
                ((uint32_t*)Ch)[((size_t)(row + 8) * N + col) >> 1] = hw;
                ((uint32_t*)Cl)[((size_t)(row + 8) * N + col) >> 1] = lw;
            }
        }
    }
}

// ---------------------------------------------------------------------------
// RoPE helper: float4 at dim c (>=128) of a 192-dim q/k head vector.
// ---------------------------------------------------------------------------
__device__ __forceinline__ float4 rope4(float4 v, float4 p, int c, int s) {
    int j = c - 128;
    bool first = (j < 32);
    int jb = first ? j : (j - 32);
    float4 r;
#pragma unroll
    for (int e = 0; e < 4; e++) {
        float inv = __expf(-(float)(jb + e) * (9.210340371976184f / 32.f));
        float ang = (float)s * inv;
        float cs, sn;
        __sincosf(ang, &sn, &cs);
        float ve = (e == 0) ? v.x : (e == 1) ? v.y : (e == 2) ? v.z : v.w;
        float pe = (e == 0) ? p.x : (e == 1) ? p.y : (e == 2) ? p.z : p.w;
        float o = first ? (ve * cs - pe * sn) : (ve * cs + pe * sn);
        if (e == 0) r.x = o; else if (e == 1) r.y = o; else if (e == 2) r.z = o; else r.w = o;
    }
    return r;
}

// Q: rope + scale + split, g_qfull -> g_qh/g_ql (same layout)
__global__ __launch_bounds__(256) void qsplit_kernel()
{
    const float scale = 0.07216878364870323f;   // 1/sqrt(192)
    size_t f = (size_t)blockIdx.x * 256 + threadIdx.x;   // float4 index
    int w = (int)(f % 768);
    int c = (w % 48) * 4;
    int row = (int)(f / 768);
    int s = row & (S_ - 1);
    float4 v = *(const float4*)&g_qfull[f * 4];
    if (c >= 128) {
        float4 p = (c < 160) ? *(const float4*)&g_qfull[f * 4 + 32]
                             : *(const float4*)&g_qfull[f * 4 - 32];
        v = rope4(v, p, c, s);
    }
    v.x *= scale; v.y *= scale; v.z *= scale; v.w *= scale;
    uint32_t h0, l0, h1, l1;
    split_pair(v.x, v.y, h0, l0);
    split_pair(v.z, v.w, h1, l1);
    ((uint2*)g_qh)[f] = make_uint2(h0, h1);
    ((uint2*)g_ql)[f] = make_uint2(l0, l1);
}

// K: rope + split, g_kvfull K-slice -> g_kh/g_kl [row][h*192+c]
__global__ __launch_bounds__(256) void ksplit_kernel()
{
    size_t f = (size_t)blockIdx.x * 256 + threadIdx.x;   // unit = 4 floats
    int c4 = (int)(f % 48);
    int h  = (int)((f / 48) % NH);
    int row = (int)(f / 768);
    int s = row & (S_ - 1);
    int c = c4 * 4;
    size_t base = (size_t)row * KVFD + h * KVD + c;
    float4 v = *(const float4*)&g_kvfull[base];
    if (c >= 128) {
        float4 p = (c < 160) ? *(const float4*)&g_kvfull[base + 32]
                             : *(const float4*)&g_kvfull[base - 32];
        v = rope4(v, p, c, s);
    }
    uint32_t h0, l0, h1, l1;
    split_pair(v.x, v.y, h0, l0);
    split_pair(v.z, v.w, h1, l1);
    size_t o = ((size_t)row * (NH*DQK) + h * DQK + c) >> 2;
    ((uint2*)g_kh)[o] = make_uint2(h0, h1);
    ((uint2*)g_kl)[o] = make_uint2(l0, l1);
}

// V transpose+split: g_kvfull V-slice [s][d] -> g_vth/g_vtl [bh][d][s]
__global__ __launch_bounds__(256) void vtsplit_kernel()
{
    __shared__ float tile[32][33];
    int s0 = blockIdx.x * 32, d0 = blockIdx.y * 32, bh = blockIdx.z;
    int b = bh >> 4, h = bh & 15;
    int tx = threadIdx.x, ty = threadIdx.y;
#pragma unroll
    for (int i = ty; i < 32; i += 8)
        tile[i][tx] = g_kvfull[(size_t)(b * S_ + s0 + i) * KVFD + h * KVD + DH + DR + d0 + tx];
    __syncthreads();
#pragma unroll
    for (int i = ty; i < 32; i += 8) {
        float v = tile[tx][i];
        uint32_t bbits = __float_as_uint(v);
        float res = v - __uint_as_float(bbits & 0xFFFF0000u);
        size_t o = ((size_t)bh * DH + d0 + i) * S_ + s0 + tx;
        g_vth[o] = (unsigned short)(bbits >> 16);
        g_vtl[o] = (unsigned short)(__float_as_uint(res) >> 16);
    }
}

// ---------------------------------------------------------------------------
// HMMA flash attention (causal): BM=128, BN=64, 8 warps (16 q-rows each).
// Split-bf16 3-term QK and PV; P stays in registers. Output: ctx planes.
// ---------------------------------------------------------------------------
#define QW 100                 // Q/K smem row stride in words (== 4 mod 32)
#define VW 36                  // VT smem row stride in words  (== 4 mod 32)
#define SM_QH  0
#define SM_QL  12800
#define SM_KH  25600
#define SM_KL  32000
#define SM_VTH 38400
#define SM_VTL 43008
#define ATTN_SMEM_BYTES (47616 * 4)    // 190,464 B

__global__ __launch_bounds__(256, 1) void attn_mma_kernel()
{
    extern __shared__ uint32_t smw[];
    const int qt  = gridDim.x - 1 - blockIdx.x;   // long blocks first
    const int h   = blockIdx.y;
    const int b   = blockIdx.z;
    const int tid = threadIdx.x;
    const int lane = tid & 31, wid = tid >> 5;
    const int g = lane >> 2, t = lane & 3;
    const int qs0 = qt * 128;
    const int mr  = wid * 16;
    const int bh  = b * NH + h;

    const uint32_t sbase = (uint32_t)__cvta_generic_to_shared(smw);
    const uint32_t aQh = sbase + (SM_QH + (mr + (lane & 15)) * QW + ((lane >> 4) << 2)) * 4;
    const uint32_t aQl = aQh + (SM_QL - SM_QH) * 4;
    const int      bRow = (lane & 7) + ((lane >> 4) & 1) * 8;
    const uint32_t bWrd = ((lane >> 3) & 1) * 4;
    const uint32_t aKh = sbase + (SM_KH + bRow * QW + bWrd) * 4;
    const uint32_t aKl = aKh + (SM_KL - SM_KH) * 4;
    const uint32_t aVh = sbase + (SM_VTH + bRow * VW + bWrd) * 4;
    const uint32_t aVl = aVh + (SM_VTL - SM_VTH) * 4;

    // Stage Q (hi/lo): 128 rows x 24 uint4 per plane
    {
        const uint4* qh = (const uint4*)(g_qh + (size_t)(b * S_ + qs0) * (NH*DQK) + h * DQK);
        const uint4* ql = (const uint4*)(g_ql + (size_t)(b * S_ + qs0) * (NH*DQK) + h * DQK);
        for (int f = tid; f < 128 * 24; f += 256) {
            int r = f / 24, w = f % 24;
            *(uint4*)(smw + SM_QH + r * QW + w * 4) = qh[(size_t)r * 384 + w];
            *(uint4*)(smw + SM_QL + r * QW + w * 4) = ql[(size_t)r * 384 + w];
        }
    }

    float m0 = -1e30f, m1 = -1e30f, l0 = 0.f, l1 = 0.f;
    float o[16][4];
#pragma unroll
    for (int nt = 0; nt < 16; nt++)
#pragma unroll
        for (int e = 0; e < 4; e++) o[nt][e] = 0.f;

    for (int kt = 0; kt <= qs0 + 64; kt += 64) {
        __syncthreads();
        {
            const uint4* kh = (const uint4*)(g_kh + (size_t)(b * S_ + kt) * (NH*DQK) + h * DQK);
            const uint4* kl = (const uint4*)(g_kl + (size_t)(b * S_ + kt) * (NH*DQK) + h * DQK);
            for (int f = tid; f < 64 * 24; f += 256) {
                int r = f / 24, w = f % 24;
                *(uint4*)(smw + SM_KH + r * QW + w * 4) = kh[(size_t)r * 384 + w];
                *(uint4*)(smw + SM_KL + r * QW + w * 4) = kl[(size_t)r * 384 + w];
            }
        }
        {
            for (int f = tid; f < 128 * 8; f += 256) {
                int d = f / 8, w = f % 8;
                const uint4* vh = (const uint4*)(g_vth + ((size_t)bh * DH + d) * S_ + kt);
                const uint4* vl = (const uint4*)(g_vtl + ((size_t)bh * DH + d) * S_ + kt);
                *(uint4*)(smw + SM_VTH + d * VW + w * 4) = vh[w];
                *(uint4*)(smw + SM_VTL + d * VW + w * 4) = vl[w];
            }
        }
        __syncthreads();

        if (kt > qs0 + mr + 15) continue;   // warp tile fully masked (warp-uniform)

        // ---- QK: S = Q K^T, 3-term split ----
        float s[8][4];
#pragma unroll
        for (int nt = 0; nt < 8; nt++)
#pragma unroll
            for (int e = 0; e < 4; e++) s[nt][e] = 0.f;

#pragma unroll
        for (int c = 0; c < 12; c++) {
            uint32_t ah[4], al[4];
            ldsm4(ah, aQh + c * 32);
            ldsm4(al, aQl + c * 32);
#pragma unroll
            for (int q = 0; q < 4; q++) {
                uint32_t kh[4], kl[4];
                ldsm4(kh, aKh + q * (16 * QW * 4) + c * 32);
                ldsm4(kl, aKl + q * (16 * QW * 4) + c * 32);
                mma_bf16(s[2*q],   ah, kh);     mma_bf16(s[2*q],   ah, kl);
                mma_bf16(s[2*q],   al, kh);
                mma_bf16(s[2*q+1], ah, kh + 2); mma_bf16(s[2*q+1], ah, kl + 2);
                mma_bf16(s[2*q+1], al, kh + 2);
            }
        }

        // causal mask (diagonal-straddling tiles only)
        if (kt >= qs0) {
            int r0 = qs0 + mr + g, r1 = r0 + 8;
#pragma unroll
            for (int nt = 0; nt < 8; nt++) {
                int c0 = kt + nt * 8 + 2 * t;
                if (c0 > r0)     s[nt][0] = -1e30f;
                if (c0 + 1 > r0) s[nt][1] = -1e30f;
                if (c0 > r1)     s[nt][2] = -1e30f;
                if (c0 + 1 > r1) s[nt][3] = -1e30f;
            }
        }

        // ---- online softmax on fragments ----
        float rm0 = -1e30f, rm1 = -1e30f;
#pragma unroll
        for (int nt = 0; nt < 8; nt++) {
            rm0 = fmaxf(rm0, fmaxf(s[nt][0], s[nt][1]));
            rm1 = fmaxf(rm1, fmaxf(s[nt][2], s[nt][3]));
        }
        rm0 = fmaxf(rm0, __shfl_xor_sync(0xffffffffu, rm0, 1));
        rm0 = fmaxf(rm0, __shfl_xor_sync(0xffffffffu, rm0, 2));
        rm1 = fmaxf(rm1, __shfl_xor_sync(0xffffffffu, rm1, 1));
        rm1 = fmaxf(rm1, __shfl_xor_sync(0xffffffffu, rm1, 2));
        float mn0 = fmaxf(m0, rm0), mn1 = fmaxf(m1, rm1);
        float corr0 = __expf(m0 - mn0), corr1 = __expf(m1 - mn1);
        m0 = mn0; m1 = mn1;

        float rs0 = 0.f, rs1 = 0.f;
#pragma unroll
        for (int nt = 0; nt < 8; nt++) {
            s[nt][0] = __expf(s[nt][0] - mn0);
            s[nt][1] = __expf(s[nt][1] - mn0);
            s[nt][2] = __expf(s[nt][2] - mn1);
            s[nt][3] = __expf(s[nt][3] - mn1);
            rs0 += s[nt][0] + s[nt][1];
            rs1 += s[nt][2] + s[nt][3];
        }
        rs0 += __shfl_xor_sync(0xffffffffu, rs0, 1);
        rs0 += __shfl_xor_sync(0xffffffffu, rs0, 2);
        rs1 += __shfl_xor_sync(0xffffffffu, rs1, 1);
        rs1 += __shfl_xor_sync(0xffffffffu, rs1, 2);
        l0 = l0 * corr0 + rs0;
        l1 = l1 * corr1 + rs1;

#pragma unroll
        for (int nt = 0; nt < 16; nt++) {
            o[nt][0] *= corr0; o[nt][1] *= corr0;
            o[nt][2] *= corr1; o[nt][3] *= corr1;
        }

        // ---- pack P into split bf16 A-fragments (registers only) ----
        uint32_t php[8][2], plp[8][2];
#pragma unroll
        for (int nt = 0; nt < 8; nt++) {
            split_pair(s[nt][0], s[nt][1], php[nt][0], plp[nt][0]);
            split_pair(s[nt][2], s[nt][3], php[nt][1], plp[nt][1]);
        }

        // ---- PV: O += P V, 3-term split ----
#pragma unroll
        for (int kc = 0; kc < 4; kc++) {
            uint32_t pah[4] = {php[2*kc][0], php[2*kc][1], php[2*kc+1][0], php[2*kc+1][1]};
            uint32_t pal[4] = {plp[2*kc][0], plp[2*kc][1], plp[2*kc+1][0], plp[2*kc+1][1]};
#pragma unroll
            for (int vq = 0; vq < 8; vq++) {
                uint32_t vh[4], vl[4];
                ldsm4(vh, aVh + vq * (16 * VW * 4) + kc * 32);
                ldsm4(vl, aVl + vq * (16 * VW * 4) + kc * 32);
                mma_bf16(o[2*vq],   pah, vh);     mma_bf16(o[2*vq],   pah, vl);
                mma_bf16(o[2*vq],   pal, vh);
                mma_bf16(o[2*vq+1], pah, vh + 2); mma_bf16(o[2*vq+1], pah, vl + 2);
                mma_bf16(o[2*vq+1], pal, vh + 2);
            }
        }
    }

    // ---- finalize + store ctx as bf16 hi/lo planes ----
    float inv0 = 1.f / l0, inv1 = 1.f / l1;
    int row0 = b * S_ + qs0 + mr + g;
#pragma unroll
    for (int nt = 0; nt < 16; nt++) {
        int col = h * DH + nt * 8 + 2 * t;
        uint32_t hw, lw;
        split_pair(o[nt][0] * inv0, o[nt][1] * inv0, hw, lw);
        ((uint32_t*)g_ctxh)[((size_t)row0 * DMODEL + col) >> 1] = hw;
        ((uint32_t*)g_ctxl)[((size_t)row0 * DMODEL + col) >> 1] = lw;
        split_pair(o[nt][2] * inv1, o[nt][3] * inv1, hw, lw);
        ((uint32_t*)g_ctxh)[((size_t)(row0 + 8) * DMODEL + col) >> 1] = hw;
        ((uint32_t*)g_ctxl)[((size_t)(row0 + 8) * DMODEL + col) >> 1] = lw;
    }
}

// ---------------------------------------------------------------------------
// Launch
// ---------------------------------------------------------------------------
extern "C" void kernel_launch(void* const* d_in, const int* in_sizes, int n_in,
                              void* d_out, int out_size)
{
    (void)in_sizes; (void)n_in; (void)out_size;
    const float* x    = (const float*)d_in[0];
    const float* Wkvd = (const float*)d_in[1];
    const float* Wkvu = (const float*)d_in[2];
    const float* Wqd  = (const float*)d_in[3];
    const float* Wqu  = (const float*)d_in[4];
    const float* Wo   = (const float*)d_in[5];
    float* out = (float*)d_out;

    float *kvfull, *qfull;
    unsigned short *xh, *xl, *kvlath, *kvlatl, *qlath, *qlatl, *ctxh, *ctxl;
    unsigned short *wkvdH, *wkvdL, *wqdH, *wqdL, *wkvuH, *wkvuL, *wquH, *wquL, *woH, *woL;
    cudaGetSymbolAddress((void**)&kvfull, g_kvfull);
    cudaGetSymbolAddress((void**)&qfull,  g_qfull);
    cudaGetSymbolAddress((void**)&xh,     g_xh);
    cudaGetSymbolAddress((void**)&xl,     g_xl);
    cudaGetSymbolAddress((void**)&kvlath, g_kvlath);
    cudaGetSymbolAddress((void**)&kvlatl, g_kvlatl);
    cudaGetSymbolAddress((void**)&qlath,  g_qlath);
    cudaGetSymbolAddress((void**)&qlatl,  g_qlatl);
    cudaGetSymbolAddress((void**)&ctxh,   g_ctxh);
    cudaGetSymbolAddress((void**)&ctxl,   g_ctxl);
    cudaGetSymbolAddress((void**)&wkvdH,  g_wkvd_h);
    cudaGetSymbolAddress((void**)&wkvdL,  g_wkvd_l);
    cudaGetSymbolAddress((void**)&wqdH,   g_wqd_h);
    cudaGetSymbolAddress((void**)&wqdL,   g_wqd_l);
    cudaGetSymbolAddress((void**)&wkvuH,  g_wkvu_h);
    cudaGetSymbolAddress((void**)&wkvuL,  g_wkvu_l);
    cudaGetSymbolAddress((void**)&wquH,   g_wqu_h);
    cudaGetSymbolAddress((void**)&wquL,   g_wqu_l);
    cudaGetSymbolAddress((void**)&woH,    g_wo_h);
    cudaGetSymbolAddress((void**)&woL,    g_wo_l);

    dim3 tt(32, 8);
    transpose_split_kernel<<<dim3(DLAT / 32, DMODEL / 32), tt>>>(Wkvd, wkvdH, wkvdL, DMODEL, DLAT);
    transpose_split_kernel<<<dim3(DLAT / 32, DMODEL / 32), tt>>>(Wqd,  wqdH,  wqdL,  DMODEL, DLAT);
    transpose_split_kernel<<<dim3(KVFD / 32, DLAT / 32),   tt>>>(Wkvu, wkvuH, wkvuL, DLAT,  KVFD);
    transpose_split_kernel<<<dim3(QFD  / 32, DLAT / 32),   tt>>>(Wqu,  wquH,  wquL,  DLAT,  QFD);
    transpose_split_kernel<<<dim3(DMODEL / 32, DMODEL / 32), tt>>>(Wo, woH,   woL,   DMODEL, DMODEL);

    // split x once
    xsplit_kernel<<<(ROWS * (size_t)DMODEL / 4) / 256, 256>>>(x, xh, xl);

    cudaFuncSetAttribute(hmma_gemm, cudaFuncAttributeMaxDynamicSharedMemorySize, GEMM_SMEM_BYTES);
    dim3 t(256);
    // down-projections: plane in, plane out (no fp32 intermediates)
    hmma_gemm<<<dim3(DLAT / 128, ROWS / 128), t, GEMM_SMEM_BYTES>>>(xh, xl, wkvdH, wkvdL,
                                                   nullptr, kvlath, kvlatl, ROWS, DLAT, DMODEL);
    hmma_gemm<<<dim3(DLAT / 128, ROWS / 128), t, GEMM_SMEM_BYTES>>>(xh, xl, wqdH, wqdL,
                                                   nullptr, qlath, qlatl, ROWS, DLAT, DMODEL);
    // up-projections: plane in, fp32 out (rope splits need positional reads)
    hmma_gemm<<<dim3(KVFD / 128, ROWS / 128), t, GEMM_SMEM_BYTES>>>(kvlath, kvlatl, wkvuH, wkvuL,
                                                   kvfull, nullptr, nullptr, ROWS, KVFD, DLAT);
    hmma_gemm<<<dim3(QFD  / 128, ROWS / 128), t, GEMM_SMEM_BYTES>>>(qlath, qlatl, wquH, wquL,
                                                   qfull, nullptr, nullptr, ROWS, QFD, DLAT);

    // rope + split into attention planes
    qsplit_kernel<<<(ROWS * (size_t)QFD / 4) / 256, 256>>>();
    ksplit_kernel<<<(ROWS * (size_t)NH * 48) / 256, 256>>>();
    vtsplit_kernel<<<dim3(S_ / 32, DH / 32, B_ * NH), tt>>>();

    cudaFuncSetAttribute(attn_mma_kernel, cudaFuncAttributeMaxDynamicSharedMemorySize, ATTN_SMEM_BYTES);
    attn_mma_kernel<<<dim3(S_ / 128, NH, B_), 256, ATTN_SMEM_BYTES>>>();

    // output projection: ctx planes in, fp32 out
    hmma_gemm<<<dim3(DMODEL / 128, ROWS / 128), t, GEMM_SMEM_BYTES>>>(ctxh, ctxl, woH, woL,
                                                     out, nullptr, nullptr, ROWS, DMODEL, DMODEL);
}